// round 1
// baseline (speedup 1.0000x reference)
#include <cuda_runtime.h>
#include <cuda_bf16.h>
#include <math.h>

// Problem dims
#define BB 256
#define LL 128
#define DD 1024
#define HH 512
#define G4H 2048   // 4*H

// ---------------- scratch (device globals; no allocation allowed) ----------
__device__ float g_G[2][(size_t)LL * BB * G4H];     // [dir][(t*B + b)*4H + n]  pre-activations
__device__ float g_outd[2][(size_t)BB * LL * HH];   // [dir][(b*L + t)*H + j]  masked h outputs
__device__ float g_h[2][2][(size_t)BB * HH];        // [dir][parity][b*H + j]
__device__ float g_c[2][2][(size_t)BB * HH];

// ---------------- init: zero h/c parity-0 buffers ---------------------------
__global__ void init_hc_kernel() {
    int i = blockIdx.x * blockDim.x + threadIdx.x;
    if (i < BB * HH) {
        g_h[0][0][i] = 0.f; g_h[1][0][i] = 0.f;
        g_c[0][0][i] = 0.f; g_c[1][0][i] = 0.f;
    }
}

// ---------------- input-projection GEMM ------------------------------------
// G[dir][m, n] = xrow(m) . W[n, :] + bias[n],  m = t*B + b
// forward: xrow = x[b, t, :] ; backward: xrow = x[b, clip(len[b]-1-t, 0, L-1), :]
// BM=128, BN=128, BK=8, TM=TN=8, 256 threads.
__global__ __launch_bounds__(256)
void gemm_in_kernel(const float* __restrict__ X, const int* __restrict__ x_len,
                    const float* __restrict__ W, const float* __restrict__ bias,
                    int reverse)
{
    __shared__ __align__(16) float As[8][128];
    __shared__ __align__(16) float Bs[8][128];

    float* __restrict__ G = g_G[reverse];

    const int tid   = threadIdx.x;
    const int mTile = blockIdx.y * 128;
    const int nTile = blockIdx.x * 128;

    const int tr = tid >> 4;       // 0..15
    const int tc = tid & 15;       // 0..15

    // load mapping: 128 rows x 8 cols = 256 float4
    const int aRow = tid >> 1;
    const int aCol = (tid & 1) * 4;

    // resolve gathered A row
    const int m = mTile + aRow;        // = t*B + b
    const int t = m >> 8;              // B = 256
    const int b = m & 255;
    int tt = t;
    if (reverse) {
        int len = x_len[b];
        tt = len - 1 - t;
        if (tt < 0) tt = 0;
        if (tt > LL - 1) tt = LL - 1;
    }
    const float* __restrict__ arow = X + ((size_t)b * LL + tt) * DD;
    const float* __restrict__ wrow = W + (size_t)(nTile + aRow) * DD;

    float acc[8][8];
#pragma unroll
    for (int i = 0; i < 8; i++)
#pragma unroll
        for (int j = 0; j < 8; j++) acc[i][j] = 0.f;

    for (int k0 = 0; k0 < DD; k0 += 8) {
        float4 av = *(const float4*)(arow + k0 + aCol);
        float4 wv = *(const float4*)(wrow + k0 + aCol);
        As[aCol + 0][aRow] = av.x; As[aCol + 1][aRow] = av.y;
        As[aCol + 2][aRow] = av.z; As[aCol + 3][aRow] = av.w;
        Bs[aCol + 0][aRow] = wv.x; Bs[aCol + 1][aRow] = wv.y;
        Bs[aCol + 2][aRow] = wv.z; Bs[aCol + 3][aRow] = wv.w;
        __syncthreads();
#pragma unroll
        for (int k = 0; k < 8; k++) {
            float4 a0 = *(const float4*)&As[k][tr * 8];
            float4 a1 = *(const float4*)&As[k][tr * 8 + 4];
            float4 b0 = *(const float4*)&Bs[k][tc * 8];
            float4 b1 = *(const float4*)&Bs[k][tc * 8 + 4];
            float ra[8] = {a0.x, a0.y, a0.z, a0.w, a1.x, a1.y, a1.z, a1.w};
            float rb[8] = {b0.x, b0.y, b0.z, b0.w, b1.x, b1.y, b1.z, b1.w};
#pragma unroll
            for (int i = 0; i < 8; i++)
#pragma unroll
                for (int j = 0; j < 8; j++)
                    acc[i][j] = fmaf(ra[i], rb[j], acc[i][j]);
        }
        __syncthreads();
    }

#pragma unroll
    for (int i = 0; i < 8; i++) {
        const size_t mm = (size_t)(mTile + tr * 8 + i);
#pragma unroll
        for (int j = 0; j < 8; j++) {
            const int nn = nTile + tc * 8 + j;
            G[mm * G4H + nn] = acc[i][j] + bias[nn];
        }
    }
}

// ---------------- recurrent step -------------------------------------------
// One block: 64 batches x (16 hidden * 4 gates); fuses recurrent GEMM + gates.
// grid: (H/16=32, B/64=4, 2 dirs), 256 threads.
__global__ __launch_bounds__(256)
void lstm_step_kernel(const int* __restrict__ x_len,
                      const float* __restrict__ W_hh_f,
                      const float* __restrict__ W_hh_b,
                      int t)
{
    __shared__ __align__(16) float Hs[16][68];   // [k][batch]  (stride 272B = 17*16)
    __shared__ __align__(16) float Ws[16][68];   // [k][col]    col = tx*4 + gate

    const int j0  = blockIdx.x * 16;
    const int b0  = blockIdx.y * 64;
    const int dir = blockIdx.z;

    const float* __restrict__ W  = dir ? W_hh_b : W_hh_f;
    const float* __restrict__ G  = g_G[dir];
    float* __restrict__ outp     = g_outd[dir];
    const int p = t & 1;
    const float* __restrict__ hprev = g_h[dir][p];
    float* __restrict__ hnext       = g_h[dir][p ^ 1];
    const float* __restrict__ cprev = g_c[dir][p];
    float* __restrict__ cnext       = g_c[dir][p ^ 1];

    const int tid = threadIdx.x;
    const int ty = tid >> 4;   // 0..15 -> 4 batches each
    const int tx = tid & 15;   // 0..15 -> hidden j0+tx

    // load mapping: 64 rows x 16 k = 256 float4
    const int lr = tid >> 2;          // 0..63
    const int lc = (tid & 3) * 4;     // {0,4,8,12}
    const int n_ld = (lr & 3) * HH + j0 + (lr >> 2);   // W row for col lr
    const float* __restrict__ wrow = W + (size_t)n_ld * HH;
    const float* __restrict__ hrow = hprev + (size_t)(b0 + lr) * HH;

    float acc[4][4];
#pragma unroll
    for (int r = 0; r < 4; r++)
#pragma unroll
        for (int g = 0; g < 4; g++) acc[r][g] = 0.f;

    for (int k0 = 0; k0 < HH; k0 += 16) {
        float4 hv = *(const float4*)(hrow + k0 + lc);
        float4 wv = *(const float4*)(wrow + k0 + lc);
        Hs[lc + 0][lr] = hv.x; Hs[lc + 1][lr] = hv.y;
        Hs[lc + 2][lr] = hv.z; Hs[lc + 3][lr] = hv.w;
        Ws[lc + 0][lr] = wv.x; Ws[lc + 1][lr] = wv.y;
        Ws[lc + 2][lr] = wv.z; Ws[lc + 3][lr] = wv.w;
        __syncthreads();
#pragma unroll
        for (int k = 0; k < 16; k++) {
            float4 hh = *(const float4*)&Hs[k][ty * 4];
            float4 ww = *(const float4*)&Ws[k][tx * 4];
            float hr[4] = {hh.x, hh.y, hh.z, hh.w};
            float wr[4] = {ww.x, ww.y, ww.z, ww.w};
#pragma unroll
            for (int r = 0; r < 4; r++)
#pragma unroll
                for (int g = 0; g < 4; g++)
                    acc[r][g] = fmaf(hr[r], wr[g], acc[r][g]);
        }
        __syncthreads();
    }

    const int j = j0 + tx;
#pragma unroll
    for (int r = 0; r < 4; r++) {
        const int b = b0 + ty * 4 + r;
        const int len = x_len[b];
        const float* gpre = G + ((size_t)t * BB + b) * G4H;
        float gi = acc[r][0] + gpre[0 * HH + j];
        float gf = acc[r][1] + gpre[1 * HH + j];
        float gg = acc[r][2] + gpre[2 * HH + j];
        float go = acc[r][3] + gpre[3 * HH + j];
        float i_ = 1.f / (1.f + expf(-gi));
        float f_ = 1.f / (1.f + expf(-gf));
        float g_ = tanhf(gg);
        float o_ = 1.f / (1.f + expf(-go));
        const size_t hc = (size_t)b * HH + j;
        float cp = cprev[hc];
        float hp = hprev[hc];
        float cn = f_ * cp + i_ * g_;
        float hn = o_ * tanhf(cn);
        bool valid = (t < len);
        hnext[hc] = valid ? hn : hp;
        cnext[hc] = valid ? cn : cp;
        outp[((size_t)b * LL + t) * HH + j] = valid ? hn : 0.f;
    }
}

// ---------------- attention + head (one block per batch) -------------------
__global__ __launch_bounds__(256)
void final_kernel(const float* __restrict__ x, const int* __restrict__ x_len,
                  const float* __restrict__ target_word,
                  const float* __restrict__ W_h, const float* __restrict__ b_tanh,
                  const float* __restrict__ W_lin, const float* __restrict__ b_lin,
                  const float* __restrict__ W_out, const float* __restrict__ b_out,
                  float* __restrict__ out)
{
    __shared__ float s_u[LL];
    __shared__ float s_ctx[2 * HH];
    __shared__ float s_lin[512];
    __shared__ float s_red[8];
    __shared__ float s_twdot;

    const int b    = blockIdx.x;
    const int tid  = threadIdx.x;
    const int warp = tid >> 5;
    const int lane = tid & 31;
    const int len  = x_len[b];

    // ---- 1. tw dot: tw[d] = mean_k target_word[b,0,k,d]; twdot = sum tw[d]*W_h[D+d]
    {
        float partial = 0.f;
        for (int d = tid; d < DD; d += 256) {
            float s = 0.f;
#pragma unroll
            for (int k = 0; k < 5; k++)
                s += target_word[((size_t)b * 5 + k) * DD + d];
            partial = fmaf(s * 0.2f, W_h[DD + d], partial);
        }
#pragma unroll
        for (int off = 16; off; off >>= 1)
            partial += __shfl_xor_sync(0xffffffffu, partial, off);
        if (lane == 0) s_red[warp] = partial;
        __syncthreads();
        if (tid == 0) {
            float s = 0.f;
            for (int w = 0; w < 8; w++) s += s_red[w];
            s_twdot = s;
        }
        __syncthreads();
    }
    const float twdot = s_twdot;

    // ---- 2. u[t] = xe[b,t,:].W_h[:D] + twdot + b_tanh[t], mask t>=len
    for (int i = 0; i < 16; i++) {
        const int t = warp * 16 + i;
        const float* xe = x + ((size_t)b * LL + t) * DD;
        float a = 0.f;
#pragma unroll 8
        for (int q = 0; q < 32; q++) {
            int d = lane + q * 32;
            a = fmaf(xe[d], W_h[d], a);
        }
#pragma unroll
        for (int off = 16; off; off >>= 1)
            a += __shfl_xor_sync(0xffffffffu, a, off);
        if (lane == 0)
            s_u[t] = (t < len) ? (a + twdot + b_tanh[t]) : -1e6f;
    }
    __syncthreads();

    // ---- 3. softmax over L=128 (warp 0)
    if (warp == 0) {
        float v[4];
#pragma unroll
        for (int q = 0; q < 4; q++) v[q] = s_u[lane + q * 32];
        float m = fmaxf(fmaxf(v[0], v[1]), fmaxf(v[2], v[3]));
#pragma unroll
        for (int off = 16; off; off >>= 1)
            m = fmaxf(m, __shfl_xor_sync(0xffffffffu, m, off));
        float e[4], s = 0.f;
#pragma unroll
        for (int q = 0; q < 4; q++) { e[q] = expf(v[q] - m); s += e[q]; }
#pragma unroll
        for (int off = 16; off; off >>= 1)
            s += __shfl_xor_sync(0xffffffffu, s, off);
        float inv = 1.f / s;
#pragma unroll
        for (int q = 0; q < 4; q++) s_u[lane + q * 32] = e[q] * inv;
    }
    __syncthreads();

    // ---- 4. context[j] = sum_t alpha[t] * h_lstm[b,t,j]   (j in [0,1024))
    {
        float accj[4] = {0.f, 0.f, 0.f, 0.f};
        const float* outf = g_outd[0] + (size_t)b * LL * HH;
        const float* outb = g_outd[1] + (size_t)b * LL * HH;
        for (int t = 0; t < LL; t++) {
            const float a = s_u[t];
            int t2 = len - 1 - t;  // backward reversal index
            if (t2 < 0) t2 = 0;
#pragma unroll
            for (int q = 0; q < 4; q++) {
                const int j = tid + q * 256;
                float hv;
                if (j < HH) hv = outf[(size_t)t * HH + j];
                else        hv = outb[(size_t)t2 * HH + (j - HH)];
                accj[q] = fmaf(a, hv, accj[q]);
            }
        }
#pragma unroll
        for (int q = 0; q < 4; q++) s_ctx[tid + q * 256] = accj[q];
    }
    __syncthreads();

    // ---- 5. lin = relu(ctx @ W_lin^T + b_lin)   (512 outputs, K=1024)
    for (int i = 0; i < 64; i++) {
        const int o = warp * 64 + i;
        const float* wr = W_lin + (size_t)o * (2 * HH);
        float a = 0.f;
#pragma unroll 8
        for (int q = 0; q < 32; q++) {
            int d = lane + q * 32;
            a = fmaf(s_ctx[d], wr[d], a);
        }
#pragma unroll
        for (int off = 16; off; off >>= 1)
            a += __shfl_xor_sync(0xffffffffu, a, off);
        if (lane == 0) s_lin[o] = fmaxf(a + b_lin[o], 0.f);
    }
    __syncthreads();

    // ---- 6. out = lin @ W_out^T + b_out  (3 outputs, K=512)
    if (warp == 0) {
#pragma unroll
        for (int o = 0; o < 3; o++) {
            const float* wr = W_out + (size_t)o * 512;
            float a = 0.f;
#pragma unroll
            for (int q = 0; q < 16; q++) {
                int d = lane + q * 32;
                a = fmaf(s_lin[d], wr[d], a);
            }
#pragma unroll
            for (int off = 16; off; off >>= 1)
                a += __shfl_xor_sync(0xffffffffu, a, off);
            if (lane == 0) out[b * 3 + o] = a + b_out[o];
        }
    }
}

// ---------------- launch ----------------------------------------------------
extern "C" void kernel_launch(void* const* d_in, const int* in_sizes, int n_in,
                              void* d_out, int out_size)
{
    const float* x           = (const float*)d_in[0];
    const int*   x_len       = (const int*)d_in[1];
    const float* target_word = (const float*)d_in[3];
    const float* W_ih_f      = (const float*)d_in[5];
    const float* W_hh_f      = (const float*)d_in[6];
    const float* b_f         = (const float*)d_in[7];
    const float* W_ih_b      = (const float*)d_in[8];
    const float* W_hh_b      = (const float*)d_in[9];
    const float* b_b         = (const float*)d_in[10];
    const float* W_h         = (const float*)d_in[11];
    const float* b_tanh      = (const float*)d_in[12];
    const float* W_lin       = (const float*)d_in[13];
    const float* b_lin       = (const float*)d_in[14];
    const float* W_out       = (const float*)d_in[15];
    const float* b_out       = (const float*)d_in[16];
    float* out = (float*)d_out;

    init_hc_kernel<<<(BB * HH + 255) / 256, 256>>>();

    dim3 ggrid(G4H / 128, (LL * BB) / 128);   // (16, 256)
    gemm_in_kernel<<<ggrid, 256>>>(x, x_len, W_ih_f, b_f, 0);
    gemm_in_kernel<<<ggrid, 256>>>(x, x_len, W_ih_b, b_b, 1);

    dim3 sgrid(HH / 16, BB / 64, 2);          // (32, 4, 2)
    for (int t = 0; t < LL; t++)
        lstm_step_kernel<<<sgrid, 256>>>(x_len, W_hh_f, W_hh_b, t);

    final_kernel<<<BB, 256>>>(x, x_len, target_word, W_h, b_tanh,
                              W_lin, b_lin, W_out, b_out, out);
}